// round 2
// baseline (speedup 1.0000x reference)
#include <cuda_runtime.h>

#define BB 512
#define SS 200
#define EMB 256
#define NSK 300

// out[b,t,e] = mask * (qf*A[e] + att*N[e] + mast*M[e] + C[e])
// where A/N/M/C are folds of proj_w with the three tiny Linear(1,d) layers.

__global__ __launch_bounds__(256) void te_fused(const int* __restrict__ q,
                                                const int* __restrict__ r,
                                                const float* __restrict__ skill_w,
                                                const float* __restrict__ skill_b,
                                                const float* __restrict__ att_w,
                                                const float* __restrict__ att_b,
                                                const float* __restrict__ mast_w,
                                                const float* __restrict__ mast_b,
                                                const float* __restrict__ proj_w,
                                                const float* __restrict__ proj_b,
                                                float* __restrict__ out) {
    __shared__ int    s_idx[SS];            // clipped skill index
    __shared__ int    s_inc[SS];            // valid ? (1 | (r<<16)) : 0
    __shared__ float4 s_pack[SS];           // {qf, att, mast, mask}
    __shared__ __align__(16) float s_A[EMB];
    __shared__ __align__(16) float s_N[EMB];
    __shared__ __align__(16) float s_M[EMB];
    __shared__ __align__(16) float s_C[EMB];

    const int b   = blockIdx.x;
    const int tid = threadIdx.x;

    // ---- 1. load row into shared (q, r) ----
    for (int t = tid; t < SS; t += 256) {
        int qi = __ldg(q + b * SS + t);
        int ri = __ldg(r + b * SS + t);
        bool valid = (qi >= 0) && (qi < NSK);
        int ci = qi < 0 ? 0 : (qi >= NSK ? NSK - 1 : qi);
        s_idx[t] = ci;
        s_inc[t] = valid ? (1 | (ri << 16)) : 0;
        s_pack[t].x = (float)qi;
        s_pack[t].w = valid ? 1.0f : 0.0f;
    }

    // ---- 2. fold projection: each thread handles one embedding dim e = tid ----
    {
        const float* row = proj_w + tid * 64;   // proj_w is [EMB, 64] row-major
        float a = 0.f, n = 0.f, m = 0.f, c = __ldg(proj_b + tid);
#pragma unroll
        for (int i = 0; i < 21; i++) {
            float w = __ldg(row + i);
            a = fmaf(__ldg(skill_w + i), w, a);
            c = fmaf(__ldg(skill_b + i), w, c);
        }
#pragma unroll
        for (int i = 0; i < 21; i++) {
            float w = __ldg(row + 21 + i);
            n = fmaf(__ldg(att_w + i), w, n);
            c = fmaf(__ldg(att_b + i), w, c);
        }
#pragma unroll
        for (int i = 0; i < 22; i++) {
            float w = __ldg(row + 42 + i);
            m = fmaf(__ldg(mast_w + i), w, m);
            c = fmaf(__ldg(mast_b + i), w, c);
        }
        s_A[tid] = a; s_N[tid] = n; s_M[tid] = m; s_C[tid] = c;
    }
    __syncthreads();

    // ---- 3. parallel triangular running-count (no serial scan chain) ----
    // attempts[t] = #{t' <= t : idx[t']==idx[t] && valid[t']}, correct likewise.
    if (tid < SS) {
        const int myq = s_idx[tid];
        int acc = 0;  // low 16: attempts, high 16: correct (both <= 200)
#pragma unroll 4
        for (int t2 = 0; t2 <= tid; t2++) {
            if (s_idx[t2] == myq) acc += s_inc[t2];
        }
        float att = (float)(acc & 0xFFFF);
        float cor = (float)(acc >> 16);
        s_pack[tid].y = att;
        s_pack[tid].z = cor / fmaxf(att, 1.0f);
    }
    __syncthreads();

    // ---- 4. epilogue: 4 time-steps x 64 threads, float4 streaming stores ----
    const int te = tid & 63;   // which float4 of the 256-wide embedding
    const int tz = tid >> 6;   // which of 4 interleaved time steps

    const float4 A = ((const float4*)s_A)[te];
    const float4 N = ((const float4*)s_N)[te];
    const float4 M = ((const float4*)s_M)[te];
    const float4 C = ((const float4*)s_C)[te];

    float4* obase = (float4*)out + (size_t)b * SS * 64 + te;

#pragma unroll 2
    for (int t = tz; t < SS; t += 4) {
        float4 p = s_pack[t];            // {qf, att, mast, mask}
        float4 o;
        o.x = p.w * fmaf(p.x, A.x, fmaf(p.y, N.x, fmaf(p.z, M.x, C.x)));
        o.y = p.w * fmaf(p.x, A.y, fmaf(p.y, N.y, fmaf(p.z, M.y, C.y)));
        o.z = p.w * fmaf(p.x, A.z, fmaf(p.y, N.z, fmaf(p.z, M.z, C.z)));
        o.w = p.w * fmaf(p.x, A.w, fmaf(p.y, N.w, fmaf(p.z, M.w, C.w)));
        __stcs(obase + (size_t)t * 64, o);
    }
}

extern "C" void kernel_launch(void* const* d_in, const int* in_sizes, int n_in,
                              void* d_out, int out_size) {
    const int*   q       = (const int*)d_in[0];
    const int*   r       = (const int*)d_in[1];
    // d_in[2] = qry (unused by the reference output)
    const float* skill_w = (const float*)d_in[3];
    const float* skill_b = (const float*)d_in[4];
    const float* att_w   = (const float*)d_in[5];
    const float* att_b   = (const float*)d_in[6];
    const float* mast_w  = (const float*)d_in[7];
    const float* mast_b  = (const float*)d_in[8];
    const float* proj_w  = (const float*)d_in[9];
    const float* proj_b  = (const float*)d_in[10];
    float* out = (float*)d_out;

    te_fused<<<BB, 256>>>(q, r, skill_w, skill_b, att_w, att_b,
                          mast_w, mast_b, proj_w, proj_b, out);
}